// round 10
// baseline (speedup 1.0000x reference)
#include <cuda_runtime.h>
#include <cuda_fp16.h>
#include <cstdint>

#define NPTS 8192
#define DIM  128
#define NTILES2 4160           // 2080 triangle tiles x 2 column halves

// ---------------- scratch -----------------------------------------------------
static __device__ __half g_fh[(size_t)NPTS * DIM];        // fp16 features
static __device__ float  g_sq[NPTS];                      // exact fp32 row norms
static __device__ float2 g_top[(size_t)NPTS * 128 * 6];   // per-row 128 slot lists
static __device__ unsigned int g_bnd[NPTS];               // encoded s-space bound

// ---------------- helpers ------------------------------------------------------
__device__ __forceinline__ uint32_t smem_u32(const void* p) {
    uint32_t a;
    asm("{ .reg .u64 t; cvta.to.shared.u64 t, %1; cvt.u32.u64 %0, t; }"
        : "=r"(a) : "l"(p));
    return a;
}
__device__ __forceinline__ void cp16(uint32_t dst, const void* src) {
    asm volatile("cp.async.cg.shared.global [%0], [%1], 16;"
                 :: "r"(dst), "l"(src) : "memory");
}
#define CP_COMMIT() asm volatile("cp.async.commit_group;" ::: "memory")
#define CP_WAIT0()  asm volatile("cp.async.wait_group 0;" ::: "memory")

__device__ __forceinline__ void ldsm_x4(uint32_t* r, uint32_t addr) {
    asm volatile("ldmatrix.sync.aligned.m8n8.x4.shared.b16 {%0,%1,%2,%3}, [%4];"
        : "=r"(r[0]), "=r"(r[1]), "=r"(r[2]), "=r"(r[3]) : "r"(addr));
}
__device__ __forceinline__ void mma16816(float* c, const uint32_t* a,
                                         uint32_t b0, uint32_t b1) {
    asm volatile("mma.sync.aligned.m16n8k16.row.col.f32.f16.f16.f32 "
        "{%0,%1,%2,%3}, {%4,%5,%6,%7}, {%8,%9}, {%0,%1,%2,%3};"
        : "+f"(c[0]), "+f"(c[1]), "+f"(c[2]), "+f"(c[3])
        : "r"(a[0]), "r"(a[1]), "r"(a[2]), "r"(a[3]), "r"(b0), "r"(b1));
}

// order-preserving float<->uint encoding (for atomicMin on possibly-negative s)
__device__ __forceinline__ unsigned int encb(float f) {
    unsigned int u = __float_as_uint(f);
    return (u >> 31) ? ~u : (u | 0x80000000u);
}
__device__ __forceinline__ float decb(unsigned int u) {
    return __uint_as_float((u >> 31) ? (u & 0x7FFFFFFFu) : ~u);
}

// swizzled byte offset inside a tile with 256B rows (16 chunks of 16B)
__device__ __forceinline__ uint32_t swz(int row, int chunk) {
    return (uint32_t)(row * 256 + (((chunk ^ row) & 7) | (chunk & 8)) * 16);
}

// top-6 insert (value + index), ascending
__device__ __forceinline__ void ins6(float v, int idx, float* nb, int* ni) {
    if (v < nb[5]) {
        nb[5] = v; ni[5] = idx;
        #pragma unroll
        for (int k = 5; k > 0; k--) {
            if (nb[k] < nb[k - 1]) {
                float tv = nb[k]; nb[k] = nb[k - 1]; nb[k - 1] = tv;
                int   ti = ni[k]; ni[k] = ni[k - 1]; ni[k - 1] = ti;
            }
        }
    }
}

// ---------------- kernel 1: fp16 convert + norms + bound init -----------------
__global__ __launch_bounds__(256) void prep_kernel(const float* __restrict__ f) {
    int wid = threadIdx.x >> 5, lane = threadIdx.x & 31;
    int row = blockIdx.x * 8 + wid;
    float4 v = ((const float4*)f)[row * 32 + lane];
    float s = v.x * v.x + v.y * v.y + v.z * v.z + v.w * v.w;
    __half2 h0 = __floats2half2_rn(v.x, v.y);
    __half2 h1 = __floats2half2_rn(v.z, v.w);
    uint2 u;
    u.x = *(uint32_t*)&h0; u.y = *(uint32_t*)&h1;
    *(uint2*)(g_fh + (size_t)row * DIM + lane * 4) = u;
    #pragma unroll
    for (int o = 16; o; o >>= 1) s += __shfl_xor_sync(0xffffffffu, s, o);
    if (lane == 0) {
        g_sq[row] = s;
        g_bnd[row] = 0xFF800000u;       // encb(+inf)
    }
}

// ---------------- kernel 2: 128x64 symmetric fp16 tile + filtered scans -------
#define SM_A   0                           // 128 x 256 = 32768
#define SM_B   32768                       // 64 x 256  = 16384
#define SM_STG 49152                       // 128 x 66 words = 33792
#define SM_SQC 82944                       // 64 floats
#define SM_SQR 83200                       // 128 floats
#define SM_LST 83712                       // 256 x 12 floats = 12288
#define SM_TOTAL 96000

__global__ __launch_bounds__(256, 2)
void gemm_topk_kernel(float* __restrict__ out) {
    extern __shared__ char smem_[];
    char* sm = smem_;
    uint32_t sbase = smem_u32(sm);
    int tid = threadIdx.x;
    int b = blockIdx.x;
    int b2 = b >> 1, h = b & 1;

    // diagonal-major decode: d = J - I; S(d) = d*(129-d)/2 tiles precede diag d.
    // Diagonal tiles (d=0) run FIRST -> every row gets a bound in wave 1.
    int d = (int)((129.0f - sqrtf(16641.0f - 8.0f * (float)b2)) * 0.5f);
    while (d > 0 && d * (129 - d) / 2 > b2) d--;
    while ((d + 1) * (128 - d) / 2 <= b2) d++;
    int I = b2 - d * (129 - d) / 2;
    int J = I + d;
    bool diag = (d == 0);

    if (tid < 64)       ((float*)(sm + SM_SQC))[tid] = g_sq[J * 128 + h * 64 + tid];
    else if (tid < 192) ((float*)(sm + SM_SQR))[tid - 64] = g_sq[I * 128 + (tid - 64)];

    // ---- async fills ----
    {
        const char* a = (const char*)(g_fh + (size_t)(I * 128) * DIM);
        #pragma unroll
        for (int it = 0; it < 8; it++) {
            int idx = tid + it * 256;              // 0..2047
            int row = idx >> 4, ch = idx & 15;
            cp16(sbase + SM_A + swz(row, ch), a + (size_t)row * 256 + ch * 16);
        }
        if (!diag) {
            const char* bp = (const char*)(g_fh + (size_t)(J * 128 + h * 64) * DIM);
            #pragma unroll
            for (int it = 0; it < 4; it++) {
                int idx = tid + it * 256;          // 0..1023
                int row = idx >> 4, ch = idx & 15;
                cp16(sbase + SM_B + swz(row, ch), bp + (size_t)row * 256 + ch * 16);
            }
        }
        CP_COMMIT();
    }

    // ---- zero-fill slice of out (overlaps cp.async latency) ----
    {
        float4 z = make_float4(0.f, 0.f, 0.f, 0.f);
        #pragma unroll
        for (int i = 0; i < 4; i++) {
            size_t gi = ((size_t)b * 4 + i) * 256 + tid;
            if (gi < (size_t)4194304) ((float4*)out)[gi] = z;
        }
    }

    CP_WAIT0();
    __syncthreads();

    // ---- fp16 HMMA mainloop: single chain, 8 k16-steps ----
    int wq = tid >> 5, l = tid & 31;
    int wm = wq & 3, wn = wq >> 2;            // 4x2 warps: 32-row x 32-col regions
    int lrow = (l & 7) | (((l >> 3) & 1) << 3);
    int kinc = (l >> 4) & 1;

    uint32_t Abase = sbase + SM_A;
    uint32_t Bbase = diag ? (Abase + h * 16384) : (sbase + SM_B);

    float acc[2][4][4];
    #pragma unroll
    for (int mi = 0; mi < 2; mi++)
        #pragma unroll
        for (int nf = 0; nf < 4; nf++)
            #pragma unroll
            for (int q = 0; q < 4; q++) acc[mi][nf][q] = 0.0f;

    #pragma unroll
    for (int ks = 0; ks < 8; ks++) {
        int ch = ks * 2 + kinc;
        uint32_t a[2][4];
        #pragma unroll
        for (int mi = 0; mi < 2; mi++)
            ldsm_x4(a[mi], Abase + swz(wm * 32 + mi * 16 + lrow, ch));
        uint32_t bb[2][4];
        #pragma unroll
        for (int ng = 0; ng < 2; ng++)
            ldsm_x4(bb[ng], Bbase + swz(wn * 32 + ng * 16 + lrow, ch));
        #pragma unroll
        for (int mi = 0; mi < 2; mi++)
            #pragma unroll
            for (int ng = 0; ng < 2; ng++) {
                mma16816(acc[mi][ng * 2 + 0], a[mi], bb[ng][0], bb[ng][2]);
                mma16816(acc[mi][ng * 2 + 1], a[mi], bb[ng][1], bb[ng][3]);
            }
    }

    // ---- fetch per-row bounds now (fresher; hidden under staging) ----
    float bnd_row = decb(g_bnd[I * 128 + (tid >> 1)]);
    float bnd_col = diag ? 0.0f : decb(g_bnd[J * 128 + h * 64 + (tid & 63)]);

    // ---- stage s = sq_col - 2*dot (diag self-entry folded in) ----
    {
        const float* sqc = (const float*)(sm + SM_SQC);
        const float* sqr = (const float*)(sm + SM_SQR);
        #pragma unroll
        for (int mi = 0; mi < 2; mi++) {
            int r0 = wm * 32 + mi * 16 + (l >> 2);
            #pragma unroll
            for (int nf = 0; nf < 4; nf++) {
                int col = wn * 32 + nf * 8 + 2 * (l & 3);
                float2 p0, p1;
                p0.x = sqc[col]     - 2.0f * acc[mi][nf][0];
                p0.y = sqc[col + 1] - 2.0f * acc[mi][nf][1];
                p1.x = sqc[col]     - 2.0f * acc[mi][nf][2];
                p1.y = sqc[col + 1] - 2.0f * acc[mi][nf][3];
                if (diag) {
                    int cg = h * 64 + col;
                    if (r0 == cg)         p0.x = -sqr[r0];
                    if (r0 == cg + 1)     p0.y = -sqr[r0];
                    if (r0 + 8 == cg)     p1.x = -sqr[r0 + 8];
                    if (r0 + 8 == cg + 1) p1.y = -sqr[r0 + 8];
                }
                *(float2*)(sm + SM_STG + (r0 * 66 + col) * 4) = p0;
                *(float2*)(sm + SM_STG + ((r0 + 8) * 66 + col) * 4) = p1;
            }
        }
    }
    __syncthreads();

    const float* sqc = (const float*)(sm + SM_SQC);
    const float* sqr = (const float*)(sm + SM_SQR);
    float* lists = (float*)(sm + SM_LST);

    // ---- row scan: 2 threads/row, groups of 4, self-tightening filter ----
    {
        int r = tid >> 1, sh = tid & 1;
        float nb[6]; int ni[6];
        #pragma unroll
        for (int k = 0; k < 6; k++) { nb[k] = 3.0e38f; ni[k] = 0; }
        const char* srow = sm + SM_STG + (r * 66 + sh * 32) * 4;
        int cgl = J * 128 + h * 64 + sh * 32;
        #pragma unroll
        for (int g = 0; g < 8; g++) {
            float2 va = *(const float2*)(srow + g * 16);
            float2 vb = *(const float2*)(srow + g * 16 + 8);
            float thr = fminf(bnd_row, nb[5]);     // global bound AND local 6th
            float gm = fminf(fminf(va.x, va.y), fminf(vb.x, vb.y));
            if (gm <= thr) {
                if (va.x <= thr) ins6(va.x, cgl + 4 * g + 0, nb, ni);
                if (va.y <= thr) ins6(va.y, cgl + 4 * g + 1, nb, ni);
                if (vb.x <= thr) ins6(vb.x, cgl + 4 * g + 2, nb, ni);
                if (vb.y <= thr) ins6(vb.y, cgl + 4 * g + 3, nb, ni);
            }
        }
        #pragma unroll
        for (int k = 0; k < 6; k++) {
            lists[tid * 12 + k] = nb[k];
            lists[tid * 12 + 6 + k] = __int_as_float(ni[k]);
        }
    }
    __syncthreads();
    if (tid < 128) {
        float mb[6]; int mi_[6];
        #pragma unroll
        for (int k = 0; k < 6; k++) { mb[k] = 3.0e38f; mi_[k] = 0; }
        #pragma unroll
        for (int s = 0; s < 2; s++) {
            const float* L = lists + (2 * tid + s) * 12;
            #pragma unroll
            for (int k = 0; k < 6; k++)
                ins6(L[k], __float_as_int(L[6 + k]), mb, mi_);
        }
        float2* dst = g_top + ((size_t)(I * 128 + tid) * 128 + (2 * J + h)) * 6;
        #pragma unroll
        for (int k = 0; k < 6; k++) {
            float2 p; p.x = mb[k]; p.y = __int_as_float(mi_[k]);
            dst[k] = p;
        }
        if (mb[5] < 3.0e38f)
            atomicMin(&g_bnd[I * 128 + tid], encb(mb[5]));
    }

    // ---- col scan (skip on diagonal): filtered groups of 4 rows ----
    if (!diag) {
        __syncthreads();
        {
            int c = tid & 63, q = tid >> 6;
            float sjc = sqc[c];
            float nb[6]; int ni[6];
            #pragma unroll
            for (int k = 0; k < 6; k++) { nb[k] = 3.0e38f; ni[k] = 0; }
            int rbase = q * 32;
            #pragma unroll
            for (int g = 0; g < 8; g++) {
                int rr = rbase + g * 4;
                float v0 = *(const float*)(sm + SM_STG + ((rr + 0) * 66 + c) * 4) + sqr[rr + 0];
                float v1 = *(const float*)(sm + SM_STG + ((rr + 1) * 66 + c) * 4) + sqr[rr + 1];
                float v2 = *(const float*)(sm + SM_STG + ((rr + 2) * 66 + c) * 4) + sqr[rr + 2];
                float v3 = *(const float*)(sm + SM_STG + ((rr + 3) * 66 + c) * 4) + sqr[rr + 3];
                float cb = fminf(bnd_col, nb[5]) + sjc + 1e-2f;  // slack: reassoc
                float gm = fminf(fminf(v0, v1), fminf(v2, v3));
                if (gm <= cb) {
                    if (v0 <= cb) ins6(v0 - sjc, I * 128 + rr + 0, nb, ni);
                    if (v1 <= cb) ins6(v1 - sjc, I * 128 + rr + 1, nb, ni);
                    if (v2 <= cb) ins6(v2 - sjc, I * 128 + rr + 2, nb, ni);
                    if (v3 <= cb) ins6(v3 - sjc, I * 128 + rr + 3, nb, ni);
                }
            }
            #pragma unroll
            for (int k = 0; k < 6; k++) {
                lists[tid * 12 + k] = nb[k];
                lists[tid * 12 + 6 + k] = __int_as_float(ni[k]);
            }
        }
        __syncthreads();
        if (tid < 64) {
            float mb[6]; int mi_[6];
            #pragma unroll
            for (int k = 0; k < 6; k++) { mb[k] = 3.0e38f; mi_[k] = 0; }
            #pragma unroll
            for (int s = 0; s < 4; s++) {
                const float* L = lists + (s * 64 + tid) * 12;
                #pragma unroll
                for (int k = 0; k < 6; k++)
                    ins6(L[k], __float_as_int(L[6 + k]), mb, mi_);
            }
            float2* dst = g_top + ((size_t)(J * 128 + h * 64 + tid) * 128 + (2 * I + h)) * 6;
            #pragma unroll
            for (int k = 0; k < 6; k++) {
                float2 p; p.x = mb[k]; p.y = __int_as_float(mi_[k]);
                dst[k] = p;
            }
            if (mb[5] < 3.0e38f)
                atomicMin(&g_bnd[J * 128 + h * 64 + tid], encb(mb[5]));
        }
    }
}

// ---------------- kernel 3: merge valid slots, weights, scatter ---------------
__global__ __launch_bounds__(256) void merge_scatter_kernel(float* __restrict__ out) {
    int warp = threadIdx.x >> 5, l = threadIdx.x & 31;
    int r = blockIdx.x * 8 + warp;
    int J = r >> 7, hr = (r >> 6) & 1;

    float nb[6]; int ni[6];
    #pragma unroll
    for (int k = 0; k < 6; k++) { nb[k] = 3.0e38f; ni[k] = 0; }

    const float2* base = g_top + (size_t)r * 128 * 6;
    #pragma unroll
    for (int it = 0; it < 4; it++) {
        int s = l + it * 32;
        bool valid = (s >= 2 * J) || ((s & 1) == hr);
        if (valid) {
            const float4* p = (const float4*)(base + (size_t)s * 6);
            float4 p0 = p[0], p1 = p[1], p2 = p[2];
            ins6(p0.x, __float_as_int(p0.y), nb, ni);
            ins6(p0.z, __float_as_int(p0.w), nb, ni);
            ins6(p1.x, __float_as_int(p1.y), nb, ni);
            ins6(p1.z, __float_as_int(p1.w), nb, ni);
            ins6(p2.x, __float_as_int(p2.y), nb, ni);
            ins6(p2.z, __float_as_int(p2.w), nb, ni);
        }
    }
    #pragma unroll
    for (int off = 16; off; off >>= 1) {
        float tv[6]; int ti[6];
        #pragma unroll
        for (int k = 0; k < 6; k++) {
            tv[k] = __shfl_xor_sync(0xffffffffu, nb[k], off);
            ti[k] = __shfl_xor_sync(0xffffffffu, ni[k], off);
        }
        #pragma unroll
        for (int k = 0; k < 6; k++) ins6(tv[k], ti[k], nb, ni);
    }

    if (l == 0) {
        float sq_r = g_sq[r];
        float d[6];
        #pragma unroll
        for (int k = 0; k < 6; k++) d[k] = sqrtf(fmaxf(sq_r + nb[k], 1e-30f));
        float thr = d[5];
        float wv[6]; float norm = 0.0f;
        #pragma unroll
        for (int k = 0; k < 6; k++) { wv[k] = thr - d[k] + 1e-10f; norm += wv[k]; }
        float inv = 1.0f / fmaxf(norm, 1e-12f);
        #pragma unroll
        for (int k = 0; k < 6; k++)
            out[(size_t)r * NPTS + ni[k]] = wv[k] * inv;
    }
}

// ---------------- launch ------------------------------------------------------
extern "C" void kernel_launch(void* const* d_in, const int* in_sizes, int n_in,
                              void* d_out, int out_size) {
    const float* features = (const float*)d_in[0];
    float* out = (float*)d_out;
    (void)in_sizes; (void)n_in; (void)out_size;

    cudaFuncSetAttribute(gemm_topk_kernel,
                         cudaFuncAttributeMaxDynamicSharedMemorySize, SM_TOTAL);

    prep_kernel<<<NPTS / 8, 256>>>(features);
    gemm_topk_kernel<<<NTILES2, 256, SM_TOTAL>>>(out);
    merge_scatter_kernel<<<NPTS / 8, 256>>>(out);
}

// round 13
// speedup vs baseline: 2.2373x; 2.2373x over previous
#include <cuda_runtime.h>
#include <cuda_fp16.h>
#include <cstdint>

#define NPTS 8192
#define DIM  128
#define NTILES2 4160           // 2080 triangle tiles x 2 column halves

// ---------------- scratch -----------------------------------------------------
static __device__ __half    g_fh[(size_t)NPTS * DIM];        // fp16 features
static __device__ float     g_sq[NPTS];                      // exact fp32 row norms
static __device__ uint32_t  g_top[(size_t)NPTS * 128 * 6];   // per-row 128 slot key lists

// ---------------- helpers ------------------------------------------------------
__device__ __forceinline__ uint32_t smem_u32(const void* p) {
    uint32_t a;
    asm("{ .reg .u64 t; cvta.to.shared.u64 t, %1; cvt.u32.u64 %0, t; }"
        : "=r"(a) : "l"(p));
    return a;
}
__device__ __forceinline__ void cp16(uint32_t dst, const void* src) {
    asm volatile("cp.async.cg.shared.global [%0], [%1], 16;"
                 :: "r"(dst), "l"(src) : "memory");
}
#define CP_COMMIT() asm volatile("cp.async.commit_group;" ::: "memory")
#define CP_WAIT0()  asm volatile("cp.async.wait_group 0;" ::: "memory")

__device__ __forceinline__ void ldsm_x4(uint32_t* r, uint32_t addr) {
    asm volatile("ldmatrix.sync.aligned.m8n8.x4.shared.b16 {%0,%1,%2,%3}, [%4];"
        : "=r"(r[0]), "=r"(r[1]), "=r"(r[2]), "=r"(r[3]) : "r"(addr));
}
__device__ __forceinline__ void mma16816(float* c, const uint32_t* a,
                                         uint32_t b0, uint32_t b1) {
    asm volatile("mma.sync.aligned.m16n8k16.row.col.f32.f16.f16.f32 "
        "{%0,%1,%2,%3}, {%4,%5,%6,%7}, {%8,%9}, {%0,%1,%2,%3};"
        : "+f"(c[0]), "+f"(c[1]), "+f"(c[2]), "+f"(c[3])
        : "r"(a[0]), "r"(a[1]), "r"(a[2]), "r"(a[3]), "r"(b0), "r"(b1));
}

// pack: 19 high bits of order-preserving float encoding + 13-bit point index
__device__ __forceinline__ uint32_t packkey(float v, int idx) {
    uint32_t u = __float_as_uint(v);
    uint32_t m = 0x80000000u | (uint32_t)(((int32_t)u) >> 31);
    return ((u ^ m) & 0xFFFFE000u) | (uint32_t)idx;
}

// swizzled byte offset inside a tile with 256B rows (16 chunks of 16B)
__device__ __forceinline__ uint32_t swz(int row, int chunk) {
    return (uint32_t)(row * 256 + (((chunk ^ row) & 7) | (chunk & 8)) * 16);
}

// top-6 insert on packed keys, ascending
__device__ __forceinline__ void ins6u(uint32_t k, uint32_t* nb) {
    if (k < nb[5]) {
        nb[5] = k;
        #pragma unroll
        for (int i = 5; i > 0; i--) {
            uint32_t lo = min(nb[i - 1], nb[i]);
            uint32_t hi = max(nb[i - 1], nb[i]);
            nb[i - 1] = lo; nb[i] = hi;
        }
    }
}

// ---------------- kernel 1: fp16 convert + exact row norms --------------------
__global__ __launch_bounds__(256) void prep_kernel(const float* __restrict__ f) {
    int wid = threadIdx.x >> 5, lane = threadIdx.x & 31;
    int row = blockIdx.x * 8 + wid;
    float4 v = ((const float4*)f)[row * 32 + lane];
    float s = v.x * v.x + v.y * v.y + v.z * v.z + v.w * v.w;
    __half2 h0 = __floats2half2_rn(v.x, v.y);
    __half2 h1 = __floats2half2_rn(v.z, v.w);
    uint2 u;
    u.x = *(uint32_t*)&h0; u.y = *(uint32_t*)&h1;
    *(uint2*)(g_fh + (size_t)row * DIM + lane * 4) = u;
    #pragma unroll
    for (int o = 16; o; o >>= 1) s += __shfl_xor_sync(0xffffffffu, s, o);
    if (lane == 0) g_sq[row] = s;
}

// ---------------- kernel 2: 128x64 symmetric fp16 tile + key scans ------------
#define SM_A   0                           // 128 x 256 = 32768
#define SM_B   32768                       // 64 x 256  = 16384
#define SM_STG 49152                       // 128 x 66 words = 33792
#define SM_SQC 82944                       // 64 floats
#define SM_SQR 83200                       // 128 floats
#define SM_LST 83712                       // 256 x 6 u32 = 6144
#define SM_TOTAL 89856

__global__ __launch_bounds__(256, 2)
void gemm_topk_kernel(float* __restrict__ out) {
    extern __shared__ char smem_[];
    char* sm = smem_;
    uint32_t sbase = smem_u32(sm);
    int tid = threadIdx.x;
    int b = blockIdx.x;
    int b2 = b >> 1, h = b & 1;

    // triangular decode: b2 -> (I <= J)
    int bi = (int)((sqrtf(8.0f * (float)b2 + 1.0f) - 1.0f) * 0.5f);
    while ((bi + 1) * (bi + 2) / 2 <= b2) bi++;
    while (bi * (bi + 1) / 2 > b2) bi--;
    int J = bi, I = b2 - bi * (bi + 1) / 2;
    bool diag = (I == J);

    if (tid < 64)       ((float*)(sm + SM_SQC))[tid] = g_sq[J * 128 + h * 64 + tid];
    else if (tid < 192) ((float*)(sm + SM_SQR))[tid - 64] = g_sq[I * 128 + (tid - 64)];

    // ---- async fills ----
    {
        const char* a = (const char*)(g_fh + (size_t)(I * 128) * DIM);
        #pragma unroll
        for (int it = 0; it < 8; it++) {
            int idx = tid + it * 256;              // 0..2047
            int row = idx >> 4, ch = idx & 15;
            cp16(sbase + SM_A + swz(row, ch), a + (size_t)row * 256 + ch * 16);
        }
        if (!diag) {
            const char* bp = (const char*)(g_fh + (size_t)(J * 128 + h * 64) * DIM);
            #pragma unroll
            for (int it = 0; it < 4; it++) {
                int idx = tid + it * 256;          // 0..1023
                int row = idx >> 4, ch = idx & 15;
                cp16(sbase + SM_B + swz(row, ch), bp + (size_t)row * 256 + ch * 16);
            }
        }
        CP_COMMIT();
    }

    // ---- zero-fill slice of out (coverage identical to passing rounds) ----
    {
        float4 z = make_float4(0.f, 0.f, 0.f, 0.f);
        #pragma unroll
        for (int i = 0; i < 4; i++) {
            size_t gi = ((size_t)b * 4 + i) * 256 + tid;
            if (gi < (size_t)4194304) ((float4*)out)[gi] = z;
        }
    }

    CP_WAIT0();
    __syncthreads();

    // ---- fp16 HMMA mainloop: single chain, 8 k16-steps ----
    int wq = tid >> 5, l = tid & 31;
    int wm = wq & 3, wn = wq >> 2;            // 4x2 warps: 32-row x 32-col regions
    int lrow = (l & 7) | (((l >> 3) & 1) << 3);
    int kinc = (l >> 4) & 1;

    uint32_t Abase = sbase + SM_A;
    uint32_t Bbase = diag ? (Abase + h * 16384) : (sbase + SM_B);

    float acc[2][4][4];
    #pragma unroll
    for (int mi = 0; mi < 2; mi++)
        #pragma unroll
        for (int nf = 0; nf < 4; nf++)
            #pragma unroll
            for (int q = 0; q < 4; q++) acc[mi][nf][q] = 0.0f;

    #pragma unroll
    for (int ks = 0; ks < 8; ks++) {
        int ch = ks * 2 + kinc;
        uint32_t a[2][4];
        #pragma unroll
        for (int mi = 0; mi < 2; mi++)
            ldsm_x4(a[mi], Abase + swz(wm * 32 + mi * 16 + lrow, ch));
        uint32_t bb[2][4];
        #pragma unroll
        for (int ng = 0; ng < 2; ng++)
            ldsm_x4(bb[ng], Bbase + swz(wn * 32 + ng * 16 + lrow, ch));
        #pragma unroll
        for (int mi = 0; mi < 2; mi++)
            #pragma unroll
            for (int ng = 0; ng < 2; ng++) {
                mma16816(acc[mi][ng * 2 + 0], a[mi], bb[ng][0], bb[ng][2]);
                mma16816(acc[mi][ng * 2 + 1], a[mi], bb[ng][1], bb[ng][3]);
            }
    }

    // ---- stage s = sq_col - 2*dot (diag self-entry folded in) ----
    {
        const float* sqc = (const float*)(sm + SM_SQC);
        const float* sqr = (const float*)(sm + SM_SQR);
        #pragma unroll
        for (int mi = 0; mi < 2; mi++) {
            int r0 = wm * 32 + mi * 16 + (l >> 2);
            #pragma unroll
            for (int nf = 0; nf < 4; nf++) {
                int col = wn * 32 + nf * 8 + 2 * (l & 3);
                float2 p0, p1;
                p0.x = sqc[col]     - 2.0f * acc[mi][nf][0];
                p0.y = sqc[col + 1] - 2.0f * acc[mi][nf][1];
                p1.x = sqc[col]     - 2.0f * acc[mi][nf][2];
                p1.y = sqc[col + 1] - 2.0f * acc[mi][nf][3];
                if (diag) {
                    int cg = h * 64 + col;
                    if (r0 == cg)         p0.x = -sqr[r0];
                    if (r0 == cg + 1)     p0.y = -sqr[r0];
                    if (r0 + 8 == cg)     p1.x = -sqr[r0 + 8];
                    if (r0 + 8 == cg + 1) p1.y = -sqr[r0 + 8];
                }
                *(float2*)(sm + SM_STG + (r0 * 66 + col) * 4) = p0;
                *(float2*)(sm + SM_STG + ((r0 + 8) * 66 + col) * 4) = p1;
            }
        }
    }
    __syncthreads();

    const float* sqc = (const float*)(sm + SM_SQC);
    const float* sqr = (const float*)(sm + SM_SQR);
    uint32_t* lists = (uint32_t*)(sm + SM_LST);

    // ---- row scan: 2 threads/row x 32 cols, packed keys ----
    {
        int r = tid >> 1, sh = tid & 1;
        uint32_t nb[6];
        #pragma unroll
        for (int k = 0; k < 6; k++) nb[k] = 0xFFFFFFFFu;
        const char* srow = sm + SM_STG + (r * 66 + sh * 32) * 4;
        int cgl = J * 128 + h * 64 + sh * 32;
        #pragma unroll
        for (int i = 0; i < 16; i++) {
            float2 v = *(const float2*)(srow + i * 8);
            ins6u(packkey(v.x, cgl + 2 * i), nb);
            ins6u(packkey(v.y, cgl + 2 * i + 1), nb);
        }
        #pragma unroll
        for (int k = 0; k < 6; k++) lists[tid * 6 + k] = nb[k];
    }
    __syncthreads();
    if (tid < 128) {
        uint32_t mb[6];
        #pragma unroll
        for (int k = 0; k < 6; k++) mb[k] = 0xFFFFFFFFu;
        #pragma unroll
        for (int s = 0; s < 2; s++) {
            const uint32_t* L = lists + (2 * tid + s) * 6;
            #pragma unroll
            for (int k = 0; k < 6; k++) ins6u(L[k], mb);
        }
        uint32_t* dst = g_top + ((size_t)(I * 128 + tid) * 128 + (2 * J + h)) * 6;
        #pragma unroll
        for (int k = 0; k < 6; k++) dst[k] = mb[k];
    }

    // ---- col scan (skip on diagonal): 4 threads/col x 32 rows ----
    if (!diag) {
        __syncthreads();
        {
            int c = tid & 63, q = tid >> 6;
            float sjc = sqc[c];
            uint32_t cn[6];
            #pragma unroll
            for (int k = 0; k < 6; k++) cn[k] = 0xFFFFFFFFu;
            int rbase = q * 32;
            #pragma unroll
            for (int i = 0; i < 32; i++) {
                int rr = rbase + i;
                float sv = *(const float*)(sm + SM_STG + (rr * 66 + c) * 4);
                float v = sv - sjc + sqr[rr];
                ins6u(packkey(v, I * 128 + rr), cn);
            }
            #pragma unroll
            for (int k = 0; k < 6; k++) lists[tid * 6 + k] = cn[k];
        }
        __syncthreads();
        if (tid < 64) {
            uint32_t mb[6];
            #pragma unroll
            for (int k = 0; k < 6; k++) mb[k] = 0xFFFFFFFFu;
            #pragma unroll
            for (int s = 0; s < 4; s++) {
                const uint32_t* L = lists + (s * 64 + tid) * 6;
                #pragma unroll
                for (int k = 0; k < 6; k++) ins6u(L[k], mb);
            }
            uint32_t* dst = g_top + ((size_t)(J * 128 + h * 64 + tid) * 128 + (2 * I + h)) * 6;
            #pragma unroll
            for (int k = 0; k < 6; k++) dst[k] = mb[k];
        }
    }
}

// ---------------- kernel 3: merge valid slots, exact recompute, scatter -------
__global__ __launch_bounds__(256)
void merge_scatter_kernel(const float* __restrict__ f, float* __restrict__ out) {
    int warp = threadIdx.x >> 5, l = threadIdx.x & 31;
    int r = blockIdx.x * 8 + warp;
    int Jb = r >> 7, hr = (r >> 6) & 1;

    uint32_t nb[6];
    #pragma unroll
    for (int k = 0; k < 6; k++) nb[k] = 0xFFFFFFFFu;

    const uint32_t* base = g_top + (size_t)r * 768;     // 128 slots x 6 keys
    #pragma unroll
    for (int it = 0; it < 4; it++) {
        int s = l + it * 32;
        bool valid = (s >= 2 * Jb) || ((s & 1) == hr);
        if (valid) {
            const uint32_t* p = base + s * 6;
            #pragma unroll
            for (int k = 0; k < 6; k++) ins6u(p[k], nb);
        }
    }
    // butterfly merge: SNAPSHOT partner's full list BEFORE inserting
    // (inserting while shuffling reads partner's mutated list -> duplicates)
    #pragma unroll
    for (int off = 16; off; off >>= 1) {
        uint32_t tv[6];
        #pragma unroll
        for (int k = 0; k < 6; k++)
            tv[k] = __shfl_xor_sync(0xffffffffu, nb[k], off);
        #pragma unroll
        for (int k = 0; k < 6; k++) ins6u(tv[k], nb);
    }
    #pragma unroll
    for (int k = 0; k < 6; k++) nb[k] = __shfl_sync(0xffffffffu, nb[k], 0);

    // exact fp32 dots for the 6 selected neighbors (warp-cooperative)
    float4 fr = ((const float4*)(f + (size_t)r * DIM))[l];
    float dots[6];
    #pragma unroll
    for (int k = 0; k < 6; k++) {
        int idx = (int)(nb[k] & 0x1FFFu);
        float4 fj = ((const float4*)(f + (size_t)idx * DIM))[l];
        float p = fr.x * fj.x + fr.y * fj.y + fr.z * fj.z + fr.w * fj.w;
        #pragma unroll
        for (int o = 16; o; o >>= 1) p += __shfl_xor_sync(0xffffffffu, p, o);
        dots[k] = p;
    }

    if (l == 0) {
        float sq_r = g_sq[r];
        float d[6];
        int idxs[6];
        #pragma unroll
        for (int k = 0; k < 6; k++) {
            int idx = (int)(nb[k] & 0x1FFFu);
            idxs[k] = idx;
            if (idx == r) {
                d[k] = 1e-15f;                       // matches forced d_self^2 = 0
            } else {
                float d2 = sq_r + g_sq[idx] - 2.0f * dots[k];
                d[k] = sqrtf(fmaxf(d2, 1e-30f));
            }
        }
        float thr = d[0];
        #pragma unroll
        for (int k = 1; k < 6; k++) thr = fmaxf(thr, d[k]);
        float wv[6]; float norm = 0.0f;
        #pragma unroll
        for (int k = 0; k < 6; k++) { wv[k] = thr - d[k] + 1e-10f; norm += wv[k]; }
        float inv = 1.0f / fmaxf(norm, 1e-12f);
        #pragma unroll
        for (int k = 0; k < 6; k++)
            out[(size_t)r * NPTS + idxs[k]] = wv[k] * inv;
    }
}

// ---------------- launch ------------------------------------------------------
extern "C" void kernel_launch(void* const* d_in, const int* in_sizes, int n_in,
                              void* d_out, int out_size) {
    const float* features = (const float*)d_in[0];
    float* out = (float*)d_out;
    (void)in_sizes; (void)n_in; (void)out_size;

    cudaFuncSetAttribute(gemm_topk_kernel,
                         cudaFuncAttributeMaxDynamicSharedMemorySize, SM_TOTAL);

    prep_kernel<<<NPTS / 8, 256>>>(features);
    gemm_topk_kernel<<<NTILES2, 256, SM_TOTAL>>>(out);
    merge_scatter_kernel<<<NPTS / 8, 256>>>(features, out);
}

// round 14
// speedup vs baseline: 2.3689x; 1.0588x over previous
#include <cuda_runtime.h>
#include <cuda_fp16.h>
#include <cstdint>

#define NPTS 8192
#define DIM  128
#define NTILES 2080            // 64*65/2 triangle tiles, 128x128 each

// ---------------- scratch -----------------------------------------------------
static __device__ __half    g_fh[(size_t)NPTS * DIM];      // fp16 features
static __device__ float     g_sq[NPTS];                    // exact fp32 row norms
static __device__ uint32_t  g_top[(size_t)NPTS * 64 * 6];  // per-row 64 slot key lists

// ---------------- helpers ------------------------------------------------------
__device__ __forceinline__ uint32_t smem_u32(const void* p) {
    uint32_t a;
    asm("{ .reg .u64 t; cvta.to.shared.u64 t, %1; cvt.u32.u64 %0, t; }"
        : "=r"(a) : "l"(p));
    return a;
}
__device__ __forceinline__ void cp16(uint32_t dst, const void* src) {
    asm volatile("cp.async.cg.shared.global [%0], [%1], 16;"
                 :: "r"(dst), "l"(src) : "memory");
}
#define CP_COMMIT() asm volatile("cp.async.commit_group;" ::: "memory")
#define CP_WAIT0()  asm volatile("cp.async.wait_group 0;" ::: "memory")

__device__ __forceinline__ void ldsm_x4(uint32_t* r, uint32_t addr) {
    asm volatile("ldmatrix.sync.aligned.m8n8.x4.shared.b16 {%0,%1,%2,%3}, [%4];"
        : "=r"(r[0]), "=r"(r[1]), "=r"(r[2]), "=r"(r[3]) : "r"(addr));
}
__device__ __forceinline__ void mma16816(float* c, const uint32_t* a,
                                         uint32_t b0, uint32_t b1) {
    asm volatile("mma.sync.aligned.m16n8k16.row.col.f32.f16.f16.f32 "
        "{%0,%1,%2,%3}, {%4,%5,%6,%7}, {%8,%9}, {%0,%1,%2,%3};"
        : "+f"(c[0]), "+f"(c[1]), "+f"(c[2]), "+f"(c[3])
        : "r"(a[0]), "r"(a[1]), "r"(a[2]), "r"(a[3]), "r"(b0), "r"(b1));
}

// pack: 19 high bits of order-preserving float encoding + 13-bit point index
__device__ __forceinline__ uint32_t packkey(float v, int idx) {
    uint32_t u = __float_as_uint(v);
    uint32_t m = 0x80000000u | (uint32_t)(((int32_t)u) >> 31);
    return ((u ^ m) & 0xFFFFE000u) | (uint32_t)idx;
}

// swizzled byte offset inside a tile with 256B rows (16 chunks of 16B)
__device__ __forceinline__ uint32_t swz(int row, int chunk) {
    return (uint32_t)(row * 256 + (((chunk ^ row) & 7) | (chunk & 8)) * 16);
}

// top-6 insert on packed keys, ascending
__device__ __forceinline__ void ins6u(uint32_t k, uint32_t* nb) {
    if (k < nb[5]) {
        nb[5] = k;
        #pragma unroll
        for (int i = 5; i > 0; i--) {
            uint32_t lo = min(nb[i - 1], nb[i]);
            uint32_t hi = max(nb[i - 1], nb[i]);
            nb[i - 1] = lo; nb[i] = hi;
        }
    }
}

// ---------------- kernel 1: fp16 convert + exact row norms --------------------
__global__ __launch_bounds__(256) void prep_kernel(const float* __restrict__ f) {
    int wid = threadIdx.x >> 5, lane = threadIdx.x & 31;
    int row = blockIdx.x * 8 + wid;
    float4 v = ((const float4*)f)[row * 32 + lane];
    float s = v.x * v.x + v.y * v.y + v.z * v.z + v.w * v.w;
    __half2 h0 = __floats2half2_rn(v.x, v.y);
    __half2 h1 = __floats2half2_rn(v.z, v.w);
    uint2 u;
    u.x = *(uint32_t*)&h0; u.y = *(uint32_t*)&h1;
    *(uint2*)(g_fh + (size_t)row * DIM + lane * 4) = u;
    #pragma unroll
    for (int o = 16; o; o >>= 1) s += __shfl_xor_sync(0xffffffffu, s, o);
    if (lane == 0) g_sq[row] = s;
}

// ---------------- kernel 2: 128x128 symmetric tile, 2 col-half passes ---------
#define SM_A   0                           // 128 x 256 = 32768
#define SM_B   32768                       // 128 x 256 = 32768
#define SM_STG 65536                       // 128 x 66 words = 33792
#define SM_SQC 99328                       // 128 floats
#define SM_SQR 99840                       // 128 floats
#define SM_LST 100352                      // 256 x 6 u32 = 6144
#define SM_TOTAL 106496

__global__ __launch_bounds__(256, 2)
void gemm_topk_kernel(float* __restrict__ out) {
    extern __shared__ char smem_[];
    char* sm = smem_;
    uint32_t sbase = smem_u32(sm);
    int tid = threadIdx.x;
    int b = blockIdx.x;

    // triangular decode: b -> (I <= J)
    int bi = (int)((sqrtf(8.0f * (float)b + 1.0f) - 1.0f) * 0.5f);
    while ((bi + 1) * (bi + 2) / 2 <= b) bi++;
    while (bi * (bi + 1) / 2 > b) bi--;
    int J = bi, I = b - bi * (bi + 1) / 2;
    bool diag = (I == J);

    if (tid < 128) ((float*)(sm + SM_SQC))[tid] = g_sq[J * 128 + tid];
    else           ((float*)(sm + SM_SQR))[tid - 128] = g_sq[I * 128 + (tid - 128)];

    // ---- async fills: A (and B unless diag), 2048 cp16 each ----
    {
        const char* a = (const char*)(g_fh + (size_t)(I * 128) * DIM);
        #pragma unroll
        for (int it = 0; it < 8; it++) {
            int idx = tid + it * 256;              // 0..2047
            int row = idx >> 4, ch = idx & 15;
            cp16(sbase + SM_A + swz(row, ch), a + (size_t)row * 256 + ch * 16);
        }
        if (!diag) {
            const char* bp = (const char*)(g_fh + (size_t)(J * 128) * DIM);
            #pragma unroll
            for (int it = 0; it < 8; it++) {
                int idx = tid + it * 256;
                int row = idx >> 4, ch = idx & 15;
                cp16(sbase + SM_B + swz(row, ch), bp + (size_t)row * 256 + ch * 16);
            }
        }
        CP_COMMIT();
    }

    // ---- zero-fill slice of out (full coverage across grid) ----
    {
        float4 z = make_float4(0.f, 0.f, 0.f, 0.f);
        #pragma unroll
        for (int i = 0; i < 8; i++) {
            size_t gi = ((size_t)b * 8 + i) * 256 + tid;
            if (gi < (size_t)4194304) ((float4*)out)[gi] = z;
        }
    }

    CP_WAIT0();
    __syncthreads();

    int wq = tid >> 5, l = tid & 31;
    int wm = wq & 3, wn = wq >> 2;            // 4x2 warps: 32-row x 32-col regions
    int lrow = (l & 7) | (((l >> 3) & 1) << 3);
    int kinc = (l >> 4) & 1;

    uint32_t Abase = sbase + SM_A;

    uint32_t nb6[6];                           // persistent row top-6 (2 thr/row)
    #pragma unroll
    for (int k = 0; k < 6; k++) nb6[k] = 0xFFFFFFFFu;

    const float* sqc = (const float*)(sm + SM_SQC);
    const float* sqr = (const float*)(sm + SM_SQR);
    uint32_t* lists = (uint32_t*)(sm + SM_LST);

    #pragma unroll 1
    for (int h = 0; h < 2; h++) {
        uint32_t Bbase = (diag ? Abase : (sbase + SM_B)) + h * 16384;

        // ---- fp16 HMMA: single chain, 8 k16-steps, 128x64 half ----
        float acc[2][4][4];
        #pragma unroll
        for (int mi = 0; mi < 2; mi++)
            #pragma unroll
            for (int nf = 0; nf < 4; nf++)
                #pragma unroll
                for (int q = 0; q < 4; q++) acc[mi][nf][q] = 0.0f;

        #pragma unroll
        for (int ks = 0; ks < 8; ks++) {
            int ch = ks * 2 + kinc;
            uint32_t a[2][4];
            #pragma unroll
            for (int mi = 0; mi < 2; mi++)
                ldsm_x4(a[mi], Abase + swz(wm * 32 + mi * 16 + lrow, ch));
            uint32_t bb[2][4];
            #pragma unroll
            for (int ng = 0; ng < 2; ng++)
                ldsm_x4(bb[ng], Bbase + swz(wn * 32 + ng * 16 + lrow, ch));
            #pragma unroll
            for (int mi = 0; mi < 2; mi++)
                #pragma unroll
                for (int ng = 0; ng < 2; ng++) {
                    mma16816(acc[mi][ng * 2 + 0], a[mi], bb[ng][0], bb[ng][2]);
                    mma16816(acc[mi][ng * 2 + 1], a[mi], bb[ng][1], bb[ng][3]);
                }
        }

        // ---- stage s = sq_col - 2*dot (diag self-entry folded in) ----
        #pragma unroll
        for (int mi = 0; mi < 2; mi++) {
            int r0 = wm * 32 + mi * 16 + (l >> 2);
            #pragma unroll
            for (int nf = 0; nf < 4; nf++) {
                int col = wn * 32 + nf * 8 + 2 * (l & 3);    // local 0..63
                int cf = h * 64 + col;                        // tile col 0..127
                float2 p0, p1;
                p0.x = sqc[cf]     - 2.0f * acc[mi][nf][0];
                p0.y = sqc[cf + 1] - 2.0f * acc[mi][nf][1];
                p1.x = sqc[cf]     - 2.0f * acc[mi][nf][2];
                p1.y = sqc[cf + 1] - 2.0f * acc[mi][nf][3];
                if (diag) {
                    if (r0 == cf)         p0.x = -sqr[r0];
                    if (r0 == cf + 1)     p0.y = -sqr[r0];
                    if (r0 + 8 == cf)     p1.x = -sqr[r0 + 8];
                    if (r0 + 8 == cf + 1) p1.y = -sqr[r0 + 8];
                }
                *(float2*)(sm + SM_STG + (r0 * 66 + col) * 4) = p0;
                *(float2*)(sm + SM_STG + ((r0 + 8) * 66 + col) * 4) = p1;
            }
        }
        __syncthreads();

        // ---- row scan into persistent nb6: 2 threads/row x 32 cols ----
        {
            int r = tid >> 1, sh = tid & 1;
            const char* srow = sm + SM_STG + (r * 66 + sh * 32) * 4;
            int cgl = J * 128 + h * 64 + sh * 32;
            #pragma unroll
            for (int i = 0; i < 16; i++) {
                float2 v = *(const float2*)(srow + i * 8);
                ins6u(packkey(v.x, cgl + 2 * i), nb6);
                ins6u(packkey(v.y, cgl + 2 * i + 1), nb6);
            }
        }

        // ---- col scan (skip on diagonal): 4 threads/col x 32 rows ----
        if (!diag) {
            int c = tid & 63, q = tid >> 6;
            float sjc = sqc[h * 64 + c];
            uint32_t cn[6];
            #pragma unroll
            for (int k = 0; k < 6; k++) cn[k] = 0xFFFFFFFFu;
            int rbase = q * 32;
            #pragma unroll
            for (int i = 0; i < 32; i++) {
                int rr = rbase + i;
                float sv = *(const float*)(sm + SM_STG + (rr * 66 + c) * 4);
                float v = sv - sjc + sqr[rr];
                ins6u(packkey(v, I * 128 + rr), cn);
            }
            #pragma unroll
            for (int k = 0; k < 6; k++) lists[tid * 6 + k] = cn[k];
            __syncthreads();
            if (tid < 64) {
                uint32_t mb[6];
                #pragma unroll
                for (int k = 0; k < 6; k++) mb[k] = 0xFFFFFFFFu;
                #pragma unroll
                for (int s = 0; s < 4; s++) {
                    const uint32_t* L = lists + (s * 64 + tid) * 6;
                    #pragma unroll
                    for (int k = 0; k < 6; k++) ins6u(L[k], mb);
                }
                uint32_t* dst = g_top + ((size_t)(J * 128 + h * 64 + tid) * 64 + I) * 6;
                #pragma unroll
                for (int k = 0; k < 6; k++) dst[k] = mb[k];
            }
        }
        __syncthreads();   // STG/LST reuse in next half / final row lists
    }

    // ---- final row merge: 2 lists per row -> g_top slot J ----
    #pragma unroll
    for (int k = 0; k < 6; k++) lists[tid * 6 + k] = nb6[k];
    __syncthreads();
    if (tid < 128) {
        uint32_t mb[6];
        #pragma unroll
        for (int k = 0; k < 6; k++) mb[k] = 0xFFFFFFFFu;
        #pragma unroll
        for (int s = 0; s < 2; s++) {
            const uint32_t* L = lists + (2 * tid + s) * 6;
            #pragma unroll
            for (int k = 0; k < 6; k++) ins6u(L[k], mb);
        }
        uint32_t* dst = g_top + ((size_t)(I * 128 + tid) * 64 + J) * 6;
        #pragma unroll
        for (int k = 0; k < 6; k++) dst[k] = mb[k];
    }
}

// ---------------- kernel 3: merge 64 slots, exact recompute, scatter ----------
__global__ __launch_bounds__(256)
void merge_scatter_kernel(const float* __restrict__ f, float* __restrict__ out) {
    int warp = threadIdx.x >> 5, l = threadIdx.x & 31;
    int r = blockIdx.x * 8 + warp;

    // gather top-6 keys over 384 candidates (coalesced lane-strided reads)
    uint32_t nb[6];
    #pragma unroll
    for (int k = 0; k < 6; k++) nb[k] = 0xFFFFFFFFu;
    const uint32_t* base = g_top + (size_t)r * 384;
    #pragma unroll
    for (int i = 0; i < 12; i++) ins6u(base[l + 32 * i], nb);

    // butterfly merge: SNAPSHOT partner's full list BEFORE inserting
    #pragma unroll
    for (int off = 16; off; off >>= 1) {
        uint32_t tv[6];
        #pragma unroll
        for (int k = 0; k < 6; k++)
            tv[k] = __shfl_xor_sync(0xffffffffu, nb[k], off);
        #pragma unroll
        for (int k = 0; k < 6; k++) ins6u(tv[k], nb);
    }
    #pragma unroll
    for (int k = 0; k < 6; k++) nb[k] = __shfl_sync(0xffffffffu, nb[k], 0);

    // exact fp32 dots for the 6 selected neighbors (warp-cooperative)
    float4 fr = ((const float4*)(f + (size_t)r * DIM))[l];
    float dots[6];
    #pragma unroll
    for (int k = 0; k < 6; k++) {
        int idx = (int)(nb[k] & 0x1FFFu);
        float4 fj = ((const float4*)(f + (size_t)idx * DIM))[l];
        float p = fr.x * fj.x + fr.y * fj.y + fr.z * fj.z + fr.w * fj.w;
        #pragma unroll
        for (int o = 16; o; o >>= 1) p += __shfl_xor_sync(0xffffffffu, p, o);
        dots[k] = p;
    }

    if (l == 0) {
        float sq_r = g_sq[r];
        float d[6];
        int idxs[6];
        #pragma unroll
        for (int k = 0; k < 6; k++) {
            int idx = (int)(nb[k] & 0x1FFFu);
            idxs[k] = idx;
            if (idx == r) {
                d[k] = 1e-15f;                   // matches forced d_self^2 = 0
            } else {
                float d2 = sq_r + g_sq[idx] - 2.0f * dots[k];
                d[k] = sqrtf(fmaxf(d2, 1e-30f));
            }
        }
        float thr = d[0];
        #pragma unroll
        for (int k = 1; k < 6; k++) thr = fmaxf(thr, d[k]);
        float wv[6]; float norm = 0.0f;
        #pragma unroll
        for (int k = 0; k < 6; k++) { wv[k] = thr - d[k] + 1e-10f; norm += wv[k]; }
        float inv = 1.0f / fmaxf(norm, 1e-12f);
        #pragma unroll
        for (int k = 0; k < 6; k++)
            out[(size_t)r * NPTS + idxs[k]] = wv[k] * inv;
    }
}

// ---------------- launch ------------------------------------------------------
extern "C" void kernel_launch(void* const* d_in, const int* in_sizes, int n_in,
                              void* d_out, int out_size) {
    const float* features = (const float*)d_in[0];
    float* out = (float*)d_out;
    (void)in_sizes; (void)n_in; (void)out_size;

    cudaFuncSetAttribute(gemm_topk_kernel,
                         cudaFuncAttributeMaxDynamicSharedMemorySize, SM_TOTAL);

    prep_kernel<<<NPTS / 8, 256>>>(features);
    gemm_topk_kernel<<<NTILES, 256, SM_TOTAL>>>(out);
    merge_scatter_kernel<<<NPTS / 8, 256>>>(features, out);
}

// round 15
// speedup vs baseline: 2.4657x; 1.0409x over previous
#include <cuda_runtime.h>
#include <cuda_fp16.h>
#include <cstdint>

#define NPTS 8192
#define DIM  128
#define NTILES 2080            // 64*65/2 triangle tiles, 128x128 each
#define SQOFF 256.0f           // positivity offset (> max row norm ~190)

// ---------------- scratch -----------------------------------------------------
static __device__ __half    g_fh[(size_t)NPTS * DIM];      // fp16 features
static __device__ float     g_sq[NPTS];                    // exact fp32 row norms
static __device__ uint32_t  g_top[(size_t)NPTS * 64 * 6];  // per-row 64 slot key lists

// ---------------- helpers ------------------------------------------------------
__device__ __forceinline__ uint32_t smem_u32(const void* p) {
    uint32_t a;
    asm("{ .reg .u64 t; cvta.to.shared.u64 t, %1; cvt.u32.u64 %0, t; }"
        : "=r"(a) : "l"(p));
    return a;
}
__device__ __forceinline__ void cp16(uint32_t dst, const void* src) {
    asm volatile("cp.async.cg.shared.global [%0], [%1], 16;"
                 :: "r"(dst), "l"(src) : "memory");
}
#define CP_COMMIT() asm volatile("cp.async.commit_group;" ::: "memory")
#define CP_WAIT0()  asm volatile("cp.async.wait_group 0;" ::: "memory")

__device__ __forceinline__ void ldsm_x4(uint32_t* r, uint32_t addr) {
    asm volatile("ldmatrix.sync.aligned.m8n8.x4.shared.b16 {%0,%1,%2,%3}, [%4];"
        : "=r"(r[0]), "=r"(r[1]), "=r"(r[2]), "=r"(r[3]) : "r"(addr));
}
__device__ __forceinline__ void mma16816(float* c, const uint32_t* a,
                                         uint32_t b0, uint32_t b1) {
    asm volatile("mma.sync.aligned.m16n8k16.row.col.f32.f16.f16.f32 "
        "{%0,%1,%2,%3}, {%4,%5,%6,%7}, {%8,%9}, {%0,%1,%2,%3};"
        : "+f"(c[0]), "+f"(c[1]), "+f"(c[2]), "+f"(c[3])
        : "r"(a[0]), "r"(a[1]), "r"(a[2]), "r"(a[3]), "r"(b0), "r"(b1));
}

// pack for POSITIVE floats: raw bits are monotone -> single LOP3
__device__ __forceinline__ uint32_t packpos(float v, int idx) {
    return (__float_as_uint(v) & 0xFFFFE000u) | (uint32_t)idx;
}

// swizzled byte offset inside a tile with 256B rows (16 chunks of 16B)
__device__ __forceinline__ uint32_t swz(int row, int chunk) {
    return (uint32_t)(row * 256 + (((chunk ^ row) & 7) | (chunk & 8)) * 16);
}

// top-6 insert on packed keys, ascending
__device__ __forceinline__ void ins6u(uint32_t k, uint32_t* nb) {
    if (k < nb[5]) {
        nb[5] = k;
        #pragma unroll
        for (int i = 5; i > 0; i--) {
            uint32_t lo = min(nb[i - 1], nb[i]);
            uint32_t hi = max(nb[i - 1], nb[i]);
            nb[i - 1] = lo; nb[i] = hi;
        }
    }
}

// ---------------- kernel 1: fp16 convert + exact row norms --------------------
__global__ __launch_bounds__(256) void prep_kernel(const float* __restrict__ f) {
    int wid = threadIdx.x >> 5, lane = threadIdx.x & 31;
    int row = blockIdx.x * 8 + wid;
    float4 v = ((const float4*)f)[row * 32 + lane];
    float s = v.x * v.x + v.y * v.y + v.z * v.z + v.w * v.w;
    __half2 h0 = __floats2half2_rn(v.x, v.y);
    __half2 h1 = __floats2half2_rn(v.z, v.w);
    uint2 u;
    u.x = *(uint32_t*)&h0; u.y = *(uint32_t*)&h1;
    *(uint2*)(g_fh + (size_t)row * DIM + lane * 4) = u;
    #pragma unroll
    for (int o = 16; o; o >>= 1) s += __shfl_xor_sync(0xffffffffu, s, o);
    if (lane == 0) g_sq[row] = s;
}

// ---------------- kernel 2: 128x128 symmetric tile, 2 col-half passes ---------
#define SM_A   0                           // 128 x 256 = 32768
#define SM_B   32768                       // 128 x 256 = 32768
#define SM_STG 65536                       // 128 x 66 words = 33792
#define SM_SQC 99328                       // 128 floats (sq + SQOFF)
#define SM_SQR 99840                       // 128 floats (sq + SQOFF)
#define SM_LST 100352                      // 256 x 6 u32 = 6144 (col merge only)
#define SM_TOTAL 106496

__global__ __launch_bounds__(256, 2)
void gemm_topk_kernel(float* __restrict__ out) {
    extern __shared__ char smem_[];
    char* sm = smem_;
    uint32_t sbase = smem_u32(sm);
    int tid = threadIdx.x;
    int b = blockIdx.x;

    // triangular decode: b -> (I <= J)
    int bi = (int)((sqrtf(8.0f * (float)b + 1.0f) - 1.0f) * 0.5f);
    while ((bi + 1) * (bi + 2) / 2 <= b) bi++;
    while (bi * (bi + 1) / 2 > b) bi--;
    int J = bi, I = b - bi * (bi + 1) / 2;
    bool diag = (I == J);

    if (tid < 128) ((float*)(sm + SM_SQC))[tid] = g_sq[J * 128 + tid] + SQOFF;
    else           ((float*)(sm + SM_SQR))[tid - 128] = g_sq[I * 128 + (tid - 128)] + SQOFF;

    // ---- async fills: A (and B unless diag), 2048 cp16 each ----
    {
        const char* a = (const char*)(g_fh + (size_t)(I * 128) * DIM);
        #pragma unroll
        for (int it = 0; it < 8; it++) {
            int idx = tid + it * 256;              // 0..2047
            int row = idx >> 4, ch = idx & 15;
            cp16(sbase + SM_A + swz(row, ch), a + (size_t)row * 256 + ch * 16);
        }
        if (!diag) {
            const char* bp = (const char*)(g_fh + (size_t)(J * 128) * DIM);
            #pragma unroll
            for (int it = 0; it < 8; it++) {
                int idx = tid + it * 256;
                int row = idx >> 4, ch = idx & 15;
                cp16(sbase + SM_B + swz(row, ch), bp + (size_t)row * 256 + ch * 16);
            }
        }
        CP_COMMIT();
    }

    // ---- zero-fill slice of out (full coverage across grid) ----
    {
        float4 z = make_float4(0.f, 0.f, 0.f, 0.f);
        #pragma unroll
        for (int i = 0; i < 8; i++) {
            size_t gi = ((size_t)b * 8 + i) * 256 + tid;
            if (gi < (size_t)4194304) ((float4*)out)[gi] = z;
        }
    }

    CP_WAIT0();
    __syncthreads();

    int wq = tid >> 5, l = tid & 31;
    int wm = wq & 3, wn = wq >> 2;            // 4x2 warps: 32-row x 32-col regions
    int lrow = (l & 7) | (((l >> 3) & 1) << 3);
    int kinc = (l >> 4) & 1;

    uint32_t Abase = sbase + SM_A;

    uint32_t nb6[6];                           // persistent row top-6 (2 thr/row)
    #pragma unroll
    for (int k = 0; k < 6; k++) nb6[k] = 0xFFFFFFFFu;

    const float* sqc = (const float*)(sm + SM_SQC);
    const float* sqr = (const float*)(sm + SM_SQR);
    uint32_t* lists = (uint32_t*)(sm + SM_LST);

    #pragma unroll 1
    for (int h = 0; h < 2; h++) {
        uint32_t Bbase = (diag ? Abase : (sbase + SM_B)) + h * 16384;

        // ---- fp16 HMMA: single chain, 8 k16-steps, 128x64 half ----
        float acc[2][4][4];
        #pragma unroll
        for (int mi = 0; mi < 2; mi++)
            #pragma unroll
            for (int nf = 0; nf < 4; nf++)
                #pragma unroll
                for (int q = 0; q < 4; q++) acc[mi][nf][q] = 0.0f;

        #pragma unroll
        for (int ks = 0; ks < 8; ks++) {
            int ch = ks * 2 + kinc;
            uint32_t a[2][4];
            #pragma unroll
            for (int mi = 0; mi < 2; mi++)
                ldsm_x4(a[mi], Abase + swz(wm * 32 + mi * 16 + lrow, ch));
            uint32_t bb[2][4];
            #pragma unroll
            for (int ng = 0; ng < 2; ng++)
                ldsm_x4(bb[ng], Bbase + swz(wn * 32 + ng * 16 + lrow, ch));
            #pragma unroll
            for (int mi = 0; mi < 2; mi++)
                #pragma unroll
                for (int ng = 0; ng < 2; ng++) {
                    mma16816(acc[mi][ng * 2 + 0], a[mi], bb[ng][0], bb[ng][2]);
                    mma16816(acc[mi][ng * 2 + 1], a[mi], bb[ng][1], bb[ng][3]);
                }
        }

        // ---- stage v = (sq_col + OFF) - 2*dot  (> 0 always) ----
        // diag self-entry staged as exactly 0.0f -> minimal key, exact in merge
        #pragma unroll
        for (int mi = 0; mi < 2; mi++) {
            int r0 = wm * 32 + mi * 16 + (l >> 2);
            #pragma unroll
            for (int nf = 0; nf < 4; nf++) {
                int col = wn * 32 + nf * 8 + 2 * (l & 3);    // local 0..63
                int cf = h * 64 + col;                        // tile col 0..127
                float2 p0, p1;
                p0.x = sqc[cf]     - 2.0f * acc[mi][nf][0];
                p0.y = sqc[cf + 1] - 2.0f * acc[mi][nf][1];
                p1.x = sqc[cf]     - 2.0f * acc[mi][nf][2];
                p1.y = sqc[cf + 1] - 2.0f * acc[mi][nf][3];
                if (diag) {
                    if (r0 == cf)         p0.x = 0.0f;
                    if (r0 == cf + 1)     p0.y = 0.0f;
                    if (r0 + 8 == cf)     p1.x = 0.0f;
                    if (r0 + 8 == cf + 1) p1.y = 0.0f;
                }
                *(float2*)(sm + SM_STG + (r0 * 66 + col) * 4) = p0;
                *(float2*)(sm + SM_STG + ((r0 + 8) * 66 + col) * 4) = p1;
            }
        }
        __syncthreads();

        // ---- row scan into persistent nb6: 2 threads/row x 32 cols ----
        {
            int r = tid >> 1, sh = tid & 1;
            const char* srow = sm + SM_STG + (r * 66 + sh * 32) * 4;
            int cgl = J * 128 + h * 64 + sh * 32;
            #pragma unroll
            for (int i = 0; i < 16; i++) {
                float2 v = *(const float2*)(srow + i * 8);
                ins6u(packpos(v.x, cgl + 2 * i), nb6);
                ins6u(packpos(v.y, cgl + 2 * i + 1), nb6);
            }
        }

        // ---- col scan (skip on diagonal): 4 threads/col x 32 rows ----
        // v' = staged - (sq_c+OFF) + (sq_r+OFF) = sq_r + OFF - 2*dot  (> 0)
        if (!diag) {
            int c = tid & 63, q = tid >> 6;
            float sjc = sqc[h * 64 + c];
            uint32_t cn[6];
            #pragma unroll
            for (int k = 0; k < 6; k++) cn[k] = 0xFFFFFFFFu;
            int rbase = q * 32;
            #pragma unroll
            for (int i = 0; i < 32; i++) {
                int rr = rbase + i;
                float sv = *(const float*)(sm + SM_STG + (rr * 66 + c) * 4);
                float v = sv - sjc + sqr[rr];
                ins6u(packpos(v, I * 128 + rr), cn);
            }
            #pragma unroll
            for (int k = 0; k < 6; k++) lists[tid * 6 + k] = cn[k];
            __syncthreads();
            if (tid < 64) {
                uint32_t mb[6];
                #pragma unroll
                for (int k = 0; k < 6; k++) mb[k] = 0xFFFFFFFFu;
                #pragma unroll
                for (int s = 0; s < 4; s++) {
                    const uint32_t* L = lists + (s * 64 + tid) * 6;
                    #pragma unroll
                    for (int k = 0; k < 6; k++) ins6u(L[k], mb);
                }
                uint32_t* dst = g_top + ((size_t)(J * 128 + h * 64 + tid) * 64 + I) * 6;
                #pragma unroll
                for (int k = 0; k < 6; k++) dst[k] = mb[k];
            }
        }
        __syncthreads();   // STG/LST reuse in next half
    }

    // ---- final row merge: lane-pair shuffle (lanes 2t, 2t+1 adjacent) ----
    {
        uint32_t tv[6];
        #pragma unroll
        for (int k = 0; k < 6; k++)
            tv[k] = __shfl_xor_sync(0xffffffffu, nb6[k], 1);
        #pragma unroll
        for (int k = 0; k < 6; k++) ins6u(tv[k], nb6);
        if ((tid & 1) == 0) {
            uint32_t* dst = g_top + ((size_t)(I * 128 + (tid >> 1)) * 64 + J) * 6;
            #pragma unroll
            for (int k = 0; k < 6; k++) dst[k] = nb6[k];
        }
    }
}

// ---------------- kernel 3: merge 64 slots, exact recompute, scatter ----------
__global__ __launch_bounds__(256)
void merge_scatter_kernel(const float* __restrict__ f, float* __restrict__ out) {
    int warp = threadIdx.x >> 5, l = threadIdx.x & 31;
    int r = blockIdx.x * 8 + warp;

    // gather top-6 keys over 384 candidates (coalesced lane-strided reads)
    uint32_t nb[6];
    #pragma unroll
    for (int k = 0; k < 6; k++) nb[k] = 0xFFFFFFFFu;
    const uint32_t* base = g_top + (size_t)r * 384;
    #pragma unroll
    for (int i = 0; i < 12; i++) ins6u(base[l + 32 * i], nb);

    // butterfly merge: SNAPSHOT partner's full list BEFORE inserting
    #pragma unroll
    for (int off = 16; off; off >>= 1) {
        uint32_t tv[6];
        #pragma unroll
        for (int k = 0; k < 6; k++)
            tv[k] = __shfl_xor_sync(0xffffffffu, nb[k], off);
        #pragma unroll
        for (int k = 0; k < 6; k++) ins6u(tv[k], nb);
    }
    #pragma unroll
    for (int k = 0; k < 6; k++) nb[k] = __shfl_sync(0xffffffffu, nb[k], 0);

    // exact fp32 dots for the 6 selected neighbors (warp-cooperative)
    float4 fr = ((const float4*)(f + (size_t)r * DIM))[l];
    float dots[6];
    #pragma unroll
    for (int k = 0; k < 6; k++) {
        int idx = (int)(nb[k] & 0x1FFFu);
        float4 fj = ((const float4*)(f + (size_t)idx * DIM))[l];
        float p = fr.x * fj.x + fr.y * fj.y + fr.z * fj.z + fr.w * fj.w;
        #pragma unroll
        for (int o = 16; o; o >>= 1) p += __shfl_xor_sync(0xffffffffu, p, o);
        dots[k] = p;
    }

    if (l == 0) {
        float sq_r = g_sq[r];
        float d[6];
        int idxs[6];
        #pragma unroll
        for (int k = 0; k < 6; k++) {
            int idx = (int)(nb[k] & 0x1FFFu);
            idxs[k] = idx;
            if (idx == r) {
                d[k] = 1e-15f;                   // matches forced d_self^2 = 0
            } else {
                float d2 = sq_r + g_sq[idx] - 2.0f * dots[k];
                d[k] = sqrtf(fmaxf(d2, 1e-30f));
            }
        }
        float thr = d[0];
        #pragma unroll
        for (int k = 1; k < 6; k++) thr = fmaxf(thr, d[k]);
        float wv[6]; float norm = 0.0f;
        #pragma unroll
        for (int k = 0; k < 6; k++) { wv[k] = thr - d[k] + 1e-10f; norm += wv[k]; }
        float inv = 1.0f / fmaxf(norm, 1e-12f);
        #pragma unroll
        for (int k = 0; k < 6; k++)
            out[(size_t)r * NPTS + idxs[k]] = wv[k] * inv;
    }
}

// ---------------- launch ------------------------------------------------------
extern "C" void kernel_launch(void* const* d_in, const int* in_sizes, int n_in,
                              void* d_out, int out_size) {
    const float* features = (const float*)d_in[0];
    float* out = (float*)d_out;
    (void)in_sizes; (void)n_in; (void)out_size;

    cudaFuncSetAttribute(gemm_topk_kernel,
                         cudaFuncAttributeMaxDynamicSharedMemorySize, SM_TOTAL);

    prep_kernel<<<NPTS / 8, 256>>>(features);
    gemm_topk_kernel<<<NTILES, 256, SM_TOTAL>>>(out);
    merge_scatter_kernel<<<NPTS / 8, 256>>>(features, out);
}